// round 14
// baseline (speedup 1.0000x reference)
#include <cuda_runtime.h>
#include <cuda_bf16.h>
#include <cstdint>

#define NMAX 100000
#define EMAX 1600000
#define SF_GRID 96          // scanfill blocks (all co-resident on 148 SMs)

// Scratch (device globals — allocation-free per harness rules)
__device__ float  g_S[NMAX * 128];     // aggregated features S = A_hat * H
__device__ float  g_P[NMAX * 128];     // P = dinv .* H (layers 0,1); raw H3 (layer 2, for pool)
__device__ float  g_dinv[NMAX];
__device__ int    g_deg[NMAX];         // zeroed by previous call's pool (BSS zero on call 1)
__device__ int    g_cur[NMAX];
__device__ int    g_rptr[NMAX + 1];
__device__ int    g_col[EMAX];
__device__ int    g_blocksum[128];
__device__ int    g_done0, g_done1;
__device__ int    g_is64;

// Pre-converted bf16 W images, B-layout [n][k] with rows padded to 136 halves.
#define BROW 136
__device__ __align__(16) unsigned short g_Wb[3][2][128 * BROW];

__device__ __forceinline__ uint32_t packbf(float x0, float x1) {
    return ((uint32_t)__bfloat16_as_ushort(__float2bfloat16(x1)) << 16)
         |  (uint32_t)__bfloat16_as_ushort(__float2bfloat16(x0));
}

// ===================== L1: probe + W conversion + flag reset =====================
__global__ void k_init(const void* edge, const float* __restrict__ conv_w) {
    if (blockIdx.x == 24) {
        int t = threadIdx.x;
        if (t == 0) {
            const long long* e64 = (const long long*)edge;
            int ok = 1;
            for (int q = 0; q < 8; q++) {
                long long v = e64[q];
                if (v < 0 || v >= (1LL << 31)) ok = 0;
            }
            g_is64 = ok;
            g_done0 = 0;
            g_done1 = 0;
        }
        if (t < 128) g_blocksum[t] = -1;
        return;
    }
    // blocks 0..23: W -> bf16 hi/lo images, B layout [n][k]
    int g = blockIdx.x * 2 + (threadIdx.x >> 7);   // 0..47
    int l = g >> 4;
    int c = (g & 15) * 8;
    int n = threadIdx.x & 127;
    const float* W = conv_w + (size_t)l * 16384;
    uint32_t hi[4], lo[4];
#pragma unroll
    for (int j = 0; j < 4; j++) {
        float v0 = W[(size_t)(c + 2 * j) * 128 + n];
        float v1 = W[(size_t)(c + 2 * j + 1) * 128 + n];
        float h0 = __bfloat162float(__float2bfloat16(v0));
        float h1 = __bfloat162float(__float2bfloat16(v1));
        hi[j] = packbf(v0, v1);
        lo[j] = packbf(v0 - h0, v1 - h1);
    }
    *(uint4*)&g_Wb[l][0][n * BROW + c] = make_uint4(hi[0], hi[1], hi[2], hi[3]);
    *(uint4*)&g_Wb[l][1][n * BROW + c] = make_uint4(lo[0], lo[1], lo[2], lo[3]);
}

// ===================== L2: fused histogram + scan + dinv + CSR fill =====================
__global__ void __launch_bounds__(1024) k_scanfill(const void* edge, int E, int N) {
    __shared__ int ssum[1024];
    __shared__ int sbs[SF_GRID];
    __shared__ int sh_pref, sh_tot;

    int b = blockIdx.x, t = threadIdx.x;
    int is64 = g_is64;
    const long long* e64 = (const long long*)edge;
    const int*       e32 = (const int*)edge;

    // ---- phase 0: degree histogram ----
    for (int e = b * 1024 + t; e < E; e += SF_GRID * 1024) {
        int d = is64 ? (int)e64[E + e] : e32[E + e];
        if ((unsigned)d < (unsigned)N) atomicAdd(&g_deg[d], 1);
    }
    __threadfence();
    __syncthreads();
    if (t == 0) {
        atomicAdd(&g_done0, 1);
        while (atomicAdd(&g_done0, 0) < SF_GRID) __nanosleep(128);
    }
    __syncthreads();

    // ---- phase 1: scan (decoupled lookback) + dinv ----
    int C = (N + SF_GRID - 1) / SF_GRID;
    int base = b * C;
    int lim  = min(base + C, N);
    int i0 = base + 2 * t;                     // consecutive pair (order-correct scan)
    int i1 = i0 + 1;
    int d0 = (i0 < lim) ? g_deg[i0] : 0;
    int d1 = (i1 < lim) ? g_deg[i1] : 0;
    int part = d0 + d1;

    ssum[t] = part;
    __syncthreads();
    for (int off = 1; off < 1024; off <<= 1) {
        int v = (t >= off) ? ssum[t - off] : 0;
        __syncthreads();
        ssum[t] += v;
        __syncthreads();
    }
    int incl = ssum[t];
    int agg  = ssum[1023];

    if (t == 0) atomicExch(&g_blocksum[b], agg);

    if (t < SF_GRID) {
        int v;
        do { v = atomicAdd(&g_blocksum[t], 0); if (v != -1) break; __nanosleep(64); } while (1);
        sbs[t] = v;
    }
    __syncthreads();
    if (t == 0) {
        int p = 0, tot = 0;
        for (int j = 0; j < SF_GRID; j++) { if (j < b) p += sbs[j]; tot += sbs[j]; }
        sh_pref = p; sh_tot = tot;
    }
    __syncthreads();

    int excl = sh_pref + incl - part;
    if (i0 < lim) {
        g_rptr[i0] = excl;
        atomicExch(&g_cur[i0], excl);
        g_dinv[i0] = rsqrtf((float)(d0 + 1));  // +1 self-loop
    }
    if (i1 < lim) {
        int e1 = excl + d0;
        g_rptr[i1] = e1;
        atomicExch(&g_cur[i1], e1);
        g_dinv[i1] = rsqrtf((float)(d1 + 1));
    }
    if (b == SF_GRID - 1 && t == 0) g_rptr[N] = sh_tot;

    __threadfence();
    __syncthreads();
    if (t == 0) {
        atomicAdd(&g_done1, 1);
        while (atomicAdd(&g_done1, 0) < SF_GRID) __nanosleep(128);
    }
    __syncthreads();

    // ---- phase 2: fill (bucket src by dst) ----
    for (int e = b * 1024 + t; e < E; e += SF_GRID * 1024) {
        int s, d;
        if (is64) { s = (int)e64[e]; d = (int)e64[E + e]; }
        else      { s = e32[e];      d = e32[E + e]; }
        if ((unsigned)d < (unsigned)N) {
            int pos = atomicAdd(&g_cur[d], 1);
            g_col[pos] = ((unsigned)s < (unsigned)N) ? s : 0;
        }
    }
}

// ===================== gather: S[d] = dinv[d]*(P[d] + sum_{e:dst=d} P[src]) =====================
template<bool L0>
__global__ void __launch_bounds__(256) k_gather(const float* __restrict__ xin, int N) {
    int w = (blockIdx.x * 256 + threadIdx.x) >> 5;
    if (w >= N) return;
    int lane = threadIdx.x & 31;

    int s0 = g_rptr[w], s1 = g_rptr[w + 1];
    float dv = g_dinv[w];
    const float4* B4 = L0 ? (const float4*)xin : (const float4*)g_P;

    float4 acc = B4[(size_t)w * 32 + lane];       // self term
    if (L0) { acc.x *= dv; acc.y *= dv; acc.z *= dv; acc.w *= dv; }

    int e = s0;
    for (; e + 3 < s1; e += 4) {
        int sa = g_col[e], sb = g_col[e + 1], sc = g_col[e + 2], sd = g_col[e + 3];
        float4 va = B4[(size_t)sa * 32 + lane];
        float4 vb = B4[(size_t)sb * 32 + lane];
        float4 vc = B4[(size_t)sc * 32 + lane];
        float4 vd = B4[(size_t)sd * 32 + lane];
        if (L0) {
            float fa = g_dinv[sa], fb = g_dinv[sb], fc = g_dinv[sc], fd = g_dinv[sd];
            va.x *= fa; va.y *= fa; va.z *= fa; va.w *= fa;
            vb.x *= fb; vb.y *= fb; vb.z *= fb; vb.w *= fb;
            vc.x *= fc; vc.y *= fc; vc.z *= fc; vc.w *= fc;
            vd.x *= fd; vd.y *= fd; vd.z *= fd; vd.w *= fd;
        }
        acc.x += va.x + vb.x + vc.x + vd.x;
        acc.y += va.y + vb.y + vc.y + vd.y;
        acc.z += va.z + vb.z + vc.z + vd.z;
        acc.w += va.w + vb.w + vc.w + vd.w;
    }
    for (; e < s1; e++) {
        int s = g_col[e];
        float4 v = B4[(size_t)s * 32 + lane];
        if (L0) { float f = g_dinv[s]; v.x *= f; v.y *= f; v.z *= f; v.w *= f; }
        acc.x += v.x; acc.y += v.y; acc.z += v.z; acc.w += v.w;
    }

    acc.x *= dv; acc.y *= dv; acc.z *= dv; acc.w *= dv;
    ((float4*)g_S)[(size_t)w * 32 + lane] = acc;
}

// ===================== mma.sync GEMM: out = relu(S @ W + b) =====================
// CTA: 256 threads (8 warps), tile 128x128, K=128, 3 SMEM tiles (Ah | Al/Bl | Bh) = 102KB
// => 2 CTAs/SM (cross-CTA stage/compute overlap). Split order: Ah*Bh, Al*Bh, then the
// Al buffer is overwritten with Bl and Ah*Bl runs last (fp32 accum, order immaterial).
#define TILE_H (128 * BROW)

__device__ __forceinline__ void ksweep(const unsigned short* __restrict__ Asel,
                                       const unsigned short* __restrict__ Bsel,
                                       float acc[2][8][4], int m0, int n0,
                                       int gid, int tig) {
#pragma unroll
    for (int k = 0; k < 8; k++) {
        int k0 = k * 16;
        uint32_t a[2][4];
#pragma unroll
        for (int mf = 0; mf < 2; mf++) {
            int rr = m0 + mf * 16;
            a[mf][0] = *(const uint32_t*)&Asel[(rr + gid)     * BROW + k0 + tig * 2];
            a[mf][1] = *(const uint32_t*)&Asel[(rr + gid + 8) * BROW + k0 + tig * 2];
            a[mf][2] = *(const uint32_t*)&Asel[(rr + gid)     * BROW + k0 + 8 + tig * 2];
            a[mf][3] = *(const uint32_t*)&Asel[(rr + gid + 8) * BROW + k0 + 8 + tig * 2];
        }
        uint32_t b[8][2];
#pragma unroll
        for (int nf = 0; nf < 8; nf++) {
            int n = n0 + nf * 8 + gid;
            b[nf][0] = *(const uint32_t*)&Bsel[n * BROW + k0 + tig * 2];
            b[nf][1] = *(const uint32_t*)&Bsel[n * BROW + k0 + 8 + tig * 2];
        }
#pragma unroll
        for (int mf = 0; mf < 2; mf++)
#pragma unroll
            for (int nf = 0; nf < 8; nf++) {
                asm volatile(
                    "mma.sync.aligned.m16n8k16.row.col.f32.bf16.bf16.f32 "
                    "{%0,%1,%2,%3}, {%4,%5,%6,%7}, {%8,%9}, {%0,%1,%2,%3};"
                    : "+f"(acc[mf][nf][0]), "+f"(acc[mf][nf][1]),
                      "+f"(acc[mf][nf][2]), "+f"(acc[mf][nf][3])
                    : "r"(a[mf][0]), "r"(a[mf][1]), "r"(a[mf][2]), "r"(a[mf][3]),
                      "r"(b[nf][0]), "r"(b[nf][1]));
            }
    }
}

__global__ void __launch_bounds__(256, 2) k_gemm_mma(int layer, const float* __restrict__ bias,
                                                     int N) {
    extern __shared__ unsigned short sm[];
    int tid  = threadIdx.x;
    int lane = tid & 31;
    int wid  = tid >> 5;
    int row0 = blockIdx.x * 128;

    unsigned short* Ah = sm;                 // A hi (live whole kernel)
    unsigned short* Ax = sm + TILE_H;        // A lo, later overwritten by B lo
    unsigned short* Bh = sm + 2 * TILE_H;    // B hi

    // ---- stage A = g_S: fp32 -> bf16 hi(truncated)/lo ----
#pragma unroll
    for (int i = 0; i < 8; i++) {
        int j = tid + i * 256;
        int r = j >> 4;
        int c = (j & 15) << 3;
        float v[8];
        if (row0 + r < N) {
            float4 a = *(const float4*)(g_S + (size_t)(row0 + r) * 128 + c);
            float4 b = *(const float4*)(g_S + (size_t)(row0 + r) * 128 + c + 4);
            v[0] = a.x; v[1] = a.y; v[2] = a.z; v[3] = a.w;
            v[4] = b.x; v[5] = b.y; v[6] = b.z; v[7] = b.w;
        } else {
#pragma unroll
            for (int q = 0; q < 8; q++) v[q] = 0.f;
        }
        uint32_t hi[4], lo[4];
#pragma unroll
        for (int q = 0; q < 4; q++) {
            float x0 = v[2 * q], x1 = v[2 * q + 1];
            uint32_t u0 = __float_as_uint(x0), u1 = __float_as_uint(x1);
            hi[q] = __byte_perm(u0, u1, 0x7632);   // {hi16(x0), hi16(x1)}
            float l0 = x0 - __uint_as_float(u0 & 0xFFFF0000u);
            float l1 = x1 - __uint_as_float(u1 & 0xFFFF0000u);
            asm("cvt.rn.bf16x2.f32 %0, %1, %2;" : "=r"(lo[q]) : "f"(l1), "f"(l0));
        }
        *(uint4*)&Ah[r * BROW + c] = make_uint4(hi[0], hi[1], hi[2], hi[3]);
        *(uint4*)&Ax[r * BROW + c] = make_uint4(lo[0], lo[1], lo[2], lo[3]);
    }

    // ---- copy W hi image ----
    {
        const uint4* wh = (const uint4*)g_Wb[layer][0];
        uint4* bh = (uint4*)Bh;
        for (int j = tid; j < (TILE_H / 8); j += 256) bh[j] = wh[j];
    }
    __syncthreads();

    int wm = wid & 3;
    int wn = wid >> 2;
    int m0 = wm * 32;
    int n0 = wn * 64;
    int gid = lane >> 2;
    int tig = lane & 3;

    float acc[2][8][4];
#pragma unroll
    for (int mf = 0; mf < 2; mf++)
#pragma unroll
        for (int nf = 0; nf < 8; nf++)
#pragma unroll
            for (int q = 0; q < 4; q++) acc[mf][nf][q] = 0.f;

    ksweep(Ah, Bh, acc, m0, n0, gid, tig);   // Ah * Bh
    ksweep(Ax, Bh, acc, m0, n0, gid, tig);   // Al * Bh
    __syncthreads();                          // Al consumed everywhere

    // ---- overwrite Al buffer with B lo image ----
    {
        const uint4* wl = (const uint4*)g_Wb[layer][1];
        uint4* bl = (uint4*)Ax;
        for (int j = tid; j < (TILE_H / 8); j += 256) bl[j] = wl[j];
    }
    __syncthreads();

    ksweep(Ah, Ax, acc, m0, n0, gid, tig);   // Ah * Bl

    // ---- epilogue: bias + relu; P = out*dinv (layers 0,1) or raw out (layer 2) ----
#pragma unroll
    for (int mf = 0; mf < 2; mf++) {
        int r1 = row0 + m0 + mf * 16 + gid;
        int r2 = r1 + 8;
        float sc1 = 1.f, sc2 = 1.f;
        if (layer < 2) {
            sc1 = (r1 < N) ? g_dinv[r1] : 0.f;
            sc2 = (r2 < N) ? g_dinv[r2] : 0.f;
        }
#pragma unroll
        for (int nf = 0; nf < 8; nf++) {
            int c = n0 + nf * 8 + tig * 2;
            float2 bb = *(const float2*)(bias + c);
            if (r1 < N) {
                float v0 = fmaxf(acc[mf][nf][0] + bb.x, 0.f);
                float v1 = fmaxf(acc[mf][nf][1] + bb.y, 0.f);
                *(float2*)(g_P + (size_t)r1 * 128 + c) = make_float2(v0 * sc1, v1 * sc1);
            }
            if (r2 < N) {
                float v2 = fmaxf(acc[mf][nf][2] + bb.x, 0.f);
                float v3 = fmaxf(acc[mf][nf][3] + bb.y, 0.f);
                *(float2*)(g_P + (size_t)r2 * 128 + c) = make_float2(v2 * sc2, v3 * sc2);
            }
        }
    }
}

// ===================== pooling + output linear (+ zero g_deg for next call) =====================
__global__ void __launch_bounds__(128) k_pool_out(const void* __restrict__ batch,
                                                  const float* __restrict__ out_w,
                                                  const float* __restrict__ out_b,
                                                  float* __restrict__ out, int N) {
    for (int i = blockIdx.x * blockDim.x + threadIdx.x; i < N; i += gridDim.x * blockDim.x)
        g_deg[i] = 0;

    int g = blockIdx.x;
    int d = threadIdx.x;
    int is64 = g_is64;
    const long long* b64 = (const long long*)batch;
    const int*       b32 = (const int*)batch;

    int lo, hi;
    { int a = 0, b = N; while (a < b) { int m = (a + b) >> 1;
        int bm = is64 ? (int)b64[m] : b32[m];
        if (bm < g) a = m + 1; else b = m; } lo = a; }
    { int a = lo, b = N; while (a < b) { int m = (a + b) >> 1;
        int bm = is64 ? (int)b64[m] : b32[m];
        if (bm < g + 1) a = m + 1; else b = m; } hi = a; }

    float s = 0.f, mx = 0.f;   // relu output >= 0: max init 0 matches segment_max for non-empty segments
    for (int n = lo; n < hi; n++) {
        float v = g_P[(size_t)n * 128 + d];   // g_P holds raw H3 after layer 2
        s += v;
        mx = fmaxf(mx, v);
    }
    float cnt  = fmaxf((float)(hi - lo), 1.f);
    float mean = s / cnt;

    __shared__ float sp[128][10];
#pragma unroll
    for (int j = 0; j < 10; j++)
        sp[d][j] = mx * out_w[d * 10 + j]
                 + mean * out_w[(128 + d) * 10 + j]
                 + s * out_w[(256 + d) * 10 + j];
    __syncthreads();

    if (d < 10) {
        float r = 0.f;
        for (int i = 0; i < 128; i++) r += sp[i][d];
        out[g * 10 + d] = r + out_b[d];
    }
}

// ===================== launch =====================
extern "C" void kernel_launch(void* const* d_in, const int* in_sizes, int n_in,
                              void* d_out, int out_size) {
    const float* x      = (const float*)d_in[0];
    const void*  edge   = d_in[1];
    const void*  batch  = d_in[2];
    const float* conv_w = (const float*)d_in[3];
    const float* conv_b = (const float*)d_in[4];
    const float* out_w  = (const float*)d_in[5];
    const float* out_b  = (const float*)d_in[6];
    float*       out    = (float*)d_out;

    int N = in_sizes[0] / 128;
    int E = in_sizes[1] / 2;

    const int SMEM_BYTES = 3 * TILE_H * 2;   // 104448 -> 2 CTAs/SM
    static bool attr_done = false;
    if (!attr_done) {
        cudaFuncSetAttribute(k_gemm_mma, cudaFuncAttributeMaxDynamicSharedMemorySize, SMEM_BYTES);
        attr_done = true;
    }

    int tiles = (N + 127) / 128;
    int gblk  = (N * 32 + 255) / 256;

    k_init<<<25, 256>>>(edge, conv_w);                            // 1
    k_scanfill<<<SF_GRID, 1024>>>(edge, E, N);                    // 2 (hist+scan+fill)
    k_gather<true><<<gblk, 256>>>(x, N);                          // 3
    k_gemm_mma<<<tiles, 256, SMEM_BYTES>>>(0, conv_b, N);         // 4  <- profiled
    k_gather<false><<<gblk, 256>>>(nullptr, N);                   // 5
    k_gemm_mma<<<tiles, 256, SMEM_BYTES>>>(1, conv_b + 128, N);   // 6
    k_gather<false><<<gblk, 256>>>(nullptr, N);                   // 7
    k_gemm_mma<<<tiles, 256, SMEM_BYTES>>>(2, conv_b + 256, N);   // 8
    k_pool_out<<<256, 128>>>(batch, out_w, out_b, out, N);        // 9
}

// round 15
// speedup vs baseline: 1.0093x; 1.0093x over previous
#include <cuda_runtime.h>
#include <cuda_bf16.h>
#include <cstdint>

#define NMAX 100000
#define EMAX 1600000
#define SF_GRID 96          // scanfill blocks (all co-resident on 148 SMs)

// Scratch (device globals — allocation-free per harness rules)
__device__ float  g_S[NMAX * 128];     // aggregated features S = A_hat * H
__device__ float  g_P[NMAX * 128];     // P = dinv .* H (layers 0,1); raw H3 (layer 2, for pool)
__device__ float  g_dinv[NMAX];
__device__ int    g_deg[NMAX];         // zeroed by previous call's pool (BSS zero on call 1)
__device__ int    g_cur[NMAX];
__device__ int    g_rptr[NMAX + 1];
__device__ __align__(16) int g_col[EMAX];
__device__ int    g_blocksum[128];
__device__ int    g_done0, g_done1;
__device__ int    g_is64;

// Pre-converted bf16 W images, B-layout [n][k] with rows padded to 136 halves.
#define BROW 136
__device__ __align__(16) unsigned short g_Wb[3][2][128 * BROW];

__device__ __forceinline__ uint32_t packbf(float x0, float x1) {
    return ((uint32_t)__bfloat16_as_ushort(__float2bfloat16(x1)) << 16)
         |  (uint32_t)__bfloat16_as_ushort(__float2bfloat16(x0));
}

// ===================== L1: probe + flag reset (1 block) =====================
__global__ void k_probe(const void* edge) {
    int t = threadIdx.x;
    if (t == 0) {
        const long long* e64 = (const long long*)edge;
        int ok = 1;
        for (int q = 0; q < 8; q++) {
            long long v = e64[q];
            if (v < 0 || v >= (1LL << 31)) ok = 0;
        }
        g_is64 = ok;
        g_done0 = 0;
        g_done1 = 0;
    }
    if (t < 128) g_blocksum[t] = -1;
}

// ===================== L2: W -> bf16 hi/lo images, B layout [n][k] =====================
__global__ void k_wconv(const float* __restrict__ conv_w) {
    int g = blockIdx.x * 2 + (threadIdx.x >> 7);   // 0..47
    int l = g >> 4;
    int c = (g & 15) * 8;
    int n = threadIdx.x & 127;
    const float* W = conv_w + (size_t)l * 16384;
    uint32_t hi[4], lo[4];
#pragma unroll
    for (int j = 0; j < 4; j++) {
        float v0 = W[(size_t)(c + 2 * j) * 128 + n];
        float v1 = W[(size_t)(c + 2 * j + 1) * 128 + n];
        float h0 = __bfloat162float(__float2bfloat16(v0));
        float h1 = __bfloat162float(__float2bfloat16(v1));
        hi[j] = packbf(v0, v1);
        lo[j] = packbf(v0 - h0, v1 - h1);
    }
    *(uint4*)&g_Wb[l][0][n * BROW + c] = make_uint4(hi[0], hi[1], hi[2], hi[3]);
    *(uint4*)&g_Wb[l][1][n * BROW + c] = make_uint4(lo[0], lo[1], lo[2], lo[3]);
}

// ===================== L3: fused histogram + scan + dinv + CSR fill =====================
__global__ void __launch_bounds__(1024) k_scanfill(const void* edge, int E, int N) {
    __shared__ int ssum[1024];
    __shared__ int sbs[SF_GRID];
    __shared__ int sh_pref, sh_tot;

    int b = blockIdx.x, t = threadIdx.x;
    int is64 = g_is64;
    const long long* e64 = (const long long*)edge;
    const int*       e32 = (const int*)edge;

    // ---- phase 0: degree histogram ----
    for (int e = b * 1024 + t; e < E; e += SF_GRID * 1024) {
        int d = is64 ? (int)e64[E + e] : e32[E + e];
        if ((unsigned)d < (unsigned)N) atomicAdd(&g_deg[d], 1);
    }
    __threadfence();
    __syncthreads();
    if (t == 0) {
        atomicAdd(&g_done0, 1);
        while (atomicAdd(&g_done0, 0) < SF_GRID) __nanosleep(128);
    }
    __syncthreads();

    // ---- phase 1: scan (decoupled lookback) + dinv ----
    int C = (N + SF_GRID - 1) / SF_GRID;
    int base = b * C;
    int lim  = min(base + C, N);
    int i0 = base + 2 * t;                     // consecutive pair (order-correct scan)
    int i1 = i0 + 1;
    int d0 = (i0 < lim) ? g_deg[i0] : 0;
    int d1 = (i1 < lim) ? g_deg[i1] : 0;
    int part = d0 + d1;

    ssum[t] = part;
    __syncthreads();
    for (int off = 1; off < 1024; off <<= 1) {
        int v = (t >= off) ? ssum[t - off] : 0;
        __syncthreads();
        ssum[t] += v;
        __syncthreads();
    }
    int incl = ssum[t];
    int agg  = ssum[1023];

    if (t == 0) atomicExch(&g_blocksum[b], agg);

    if (t < SF_GRID) {
        int v;
        do { v = atomicAdd(&g_blocksum[t], 0); if (v != -1) break; __nanosleep(64); } while (1);
        sbs[t] = v;
    }
    __syncthreads();
    if (t == 0) {
        int p = 0, tot = 0;
        for (int j = 0; j < SF_GRID; j++) { if (j < b) p += sbs[j]; tot += sbs[j]; }
        sh_pref = p; sh_tot = tot;
    }
    __syncthreads();

    int excl = sh_pref + incl - part;
    if (i0 < lim) {
        g_rptr[i0] = excl;
        atomicExch(&g_cur[i0], excl);
        g_dinv[i0] = rsqrtf((float)(d0 + 1));  // +1 self-loop
    }
    if (i1 < lim) {
        int e1 = excl + d0;
        g_rptr[i1] = e1;
        atomicExch(&g_cur[i1], e1);
        g_dinv[i1] = rsqrtf((float)(d1 + 1));
    }
    if (b == SF_GRID - 1 && t == 0) g_rptr[N] = sh_tot;

    __threadfence();
    __syncthreads();
    if (t == 0) {
        atomicAdd(&g_done1, 1);
        while (atomicAdd(&g_done1, 0) < SF_GRID) __nanosleep(128);
    }
    __syncthreads();

    // ---- phase 2: fill (bucket src by dst) ----
    for (int e = b * 1024 + t; e < E; e += SF_GRID * 1024) {
        int s, d;
        if (is64) { s = (int)e64[e]; d = (int)e64[E + e]; }
        else      { s = e32[e];      d = e32[E + e]; }
        if ((unsigned)d < (unsigned)N) {
            int pos = atomicAdd(&g_cur[d], 1);
            g_col[pos] = ((unsigned)s < (unsigned)N) ? s : 0;
        }
    }
}

// ===================== gather: S[d] = dinv[d]*(P[d] + sum_{e:dst=d} P[src]) =====================
// Index loads vectorized: int4 (one LDG per 4 edges) after an alignment prologue.
template<bool L0>
__global__ void __launch_bounds__(256) k_gather(const float* __restrict__ xin, int N) {
    int w = (blockIdx.x * 256 + threadIdx.x) >> 5;
    if (w >= N) return;
    int lane = threadIdx.x & 31;

    int s0 = g_rptr[w], s1 = g_rptr[w + 1];
    float dv = g_dinv[w];
    const float4* B4 = L0 ? (const float4*)xin : (const float4*)g_P;

    float4 acc = B4[(size_t)w * 32 + lane];       // self term
    if (L0) { acc.x *= dv; acc.y *= dv; acc.z *= dv; acc.w *= dv; }

    int e = s0;
    int eAl = (s0 + 3) & ~3;                      // first 16B-aligned index slot
    if (eAl > s1) eAl = s1;
    for (; e < eAl; e++) {
        int s = g_col[e];
        float4 v = B4[((size_t)s << 5) + lane];
        if (L0) { float f = g_dinv[s]; v.x *= f; v.y *= f; v.z *= f; v.w *= f; }
        acc.x += v.x; acc.y += v.y; acc.z += v.z; acc.w += v.w;
    }
    for (; e + 3 < s1; e += 4) {
        int4 si = *(const int4*)&g_col[e];        // one vector index load per 4 edges
        float4 va = B4[((size_t)si.x << 5) + lane];
        float4 vb = B4[((size_t)si.y << 5) + lane];
        float4 vc = B4[((size_t)si.z << 5) + lane];
        float4 vd = B4[((size_t)si.w << 5) + lane];
        if (L0) {
            float fa = g_dinv[si.x], fb = g_dinv[si.y], fc = g_dinv[si.z], fd = g_dinv[si.w];
            va.x *= fa; va.y *= fa; va.z *= fa; va.w *= fa;
            vb.x *= fb; vb.y *= fb; vb.z *= fb; vb.w *= fb;
            vc.x *= fc; vc.y *= fc; vc.z *= fc; vc.w *= fc;
            vd.x *= fd; vd.y *= fd; vd.z *= fd; vd.w *= fd;
        }
        acc.x += va.x + vb.x + vc.x + vd.x;
        acc.y += va.y + vb.y + vc.y + vd.y;
        acc.z += va.z + vb.z + vc.z + vd.z;
        acc.w += va.w + vb.w + vc.w + vd.w;
    }
    for (; e < s1; e++) {
        int s = g_col[e];
        float4 v = B4[((size_t)s << 5) + lane];
        if (L0) { float f = g_dinv[s]; v.x *= f; v.y *= f; v.z *= f; v.w *= f; }
        acc.x += v.x; acc.y += v.y; acc.z += v.z; acc.w += v.w;
    }

    acc.x *= dv; acc.y *= dv; acc.z *= dv; acc.w *= dv;
    ((float4*)g_S)[(size_t)w * 32 + lane] = acc;
}

// ===================== mma.sync GEMM (R13 version): out = relu(S @ W + b) =====================
// CTA: 256 threads (8 warps), tile 128x128, K=128, 4 SMEM tiles, 1 CTA/SM.
// Split bf16 (3 products). A-staging: truncation split (hi exact via PRMT, lo via 1 cvt).
#define TILE_H (128 * BROW)

__global__ void __launch_bounds__(256, 1) k_gemm_mma(int layer, const float* __restrict__ bias,
                                                     int N) {
    extern __shared__ unsigned short sm[];
    int tid  = threadIdx.x;
    int lane = tid & 31;
    int wid  = tid >> 5;
    int row0 = blockIdx.x * 128;

    unsigned short* Ah = sm;
    unsigned short* Al = sm + TILE_H;
    unsigned short* Bh = sm + 2 * TILE_H;
    unsigned short* Bl = sm + 3 * TILE_H;

    // ---- stage A = g_S: fp32 -> bf16 hi(truncated)/lo ----
#pragma unroll
    for (int i = 0; i < 8; i++) {
        int j = tid + i * 256;
        int r = j >> 4;
        int c = (j & 15) << 3;
        float v[8];
        if (row0 + r < N) {
            float4 a = *(const float4*)(g_S + (size_t)(row0 + r) * 128 + c);
            float4 b = *(const float4*)(g_S + (size_t)(row0 + r) * 128 + c + 4);
            v[0] = a.x; v[1] = a.y; v[2] = a.z; v[3] = a.w;
            v[4] = b.x; v[5] = b.y; v[6] = b.z; v[7] = b.w;
        } else {
#pragma unroll
            for (int q = 0; q < 8; q++) v[q] = 0.f;
        }
        uint32_t hi[4], lo[4];
#pragma unroll
        for (int q = 0; q < 4; q++) {
            float x0 = v[2 * q], x1 = v[2 * q + 1];
            uint32_t u0 = __float_as_uint(x0), u1 = __float_as_uint(x1);
            hi[q] = __byte_perm(u0, u1, 0x7632);   // {hi16(x0), hi16(x1)}
            float l0 = x0 - __uint_as_float(u0 & 0xFFFF0000u);
            float l1 = x1 - __uint_as_float(u1 & 0xFFFF0000u);
            asm("cvt.rn.bf16x2.f32 %0, %1, %2;" : "=r"(lo[q]) : "f"(l1), "f"(l0));
        }
        *(uint4*)&Ah[r * BROW + c] = make_uint4(hi[0], hi[1], hi[2], hi[3]);
        *(uint4*)&Al[r * BROW + c] = make_uint4(lo[0], lo[1], lo[2], lo[3]);
    }

    // ---- copy W images ----
    {
        const uint4* wh = (const uint4*)g_Wb[layer][0];
        const uint4* wl = (const uint4*)g_Wb[layer][1];
        uint4* bh = (uint4*)Bh;
        uint4* bl = (uint4*)Bl;
        for (int j = tid; j < (TILE_H / 8); j += 256) {
            bh[j] = wh[j];
            bl[j] = wl[j];
        }
    }
    __syncthreads();

    int wm = wid & 3;
    int wn = wid >> 2;
    int m0 = wm * 32;
    int n0 = wn * 64;
    int gid = lane >> 2;
    int tig = lane & 3;

    float acc[2][8][4];
#pragma unroll
    for (int mf = 0; mf < 2; mf++)
#pragma unroll
        for (int nf = 0; nf < 8; nf++)
#pragma unroll
            for (int q = 0; q < 4; q++) acc[mf][nf][q] = 0.f;

    for (int s = 0; s < 3; s++) {
        const unsigned short* Asel = (s == 2) ? Al : Ah;
        const unsigned short* Bsel = (s == 1) ? Bl : Bh;
#pragma unroll
        for (int k = 0; k < 8; k++) {
            int k0 = k * 16;
            uint32_t a[2][4];
#pragma unroll
            for (int mf = 0; mf < 2; mf++) {
                int rr = m0 + mf * 16;
                a[mf][0] = *(const uint32_t*)&Asel[(rr + gid)     * BROW + k0 + tig * 2];
                a[mf][1] = *(const uint32_t*)&Asel[(rr + gid + 8) * BROW + k0 + tig * 2];
                a[mf][2] = *(const uint32_t*)&Asel[(rr + gid)     * BROW + k0 + 8 + tig * 2];
                a[mf][3] = *(const uint32_t*)&Asel[(rr + gid + 8) * BROW + k0 + 8 + tig * 2];
            }
            uint32_t b[8][2];
#pragma unroll
            for (int nf = 0; nf < 8; nf++) {
                int n = n0 + nf * 8 + gid;
                b[nf][0] = *(const uint32_t*)&Bsel[n * BROW + k0 + tig * 2];
                b[nf][1] = *(const uint32_t*)&Bsel[n * BROW + k0 + 8 + tig * 2];
            }
#pragma unroll
            for (int mf = 0; mf < 2; mf++)
#pragma unroll
                for (int nf = 0; nf < 8; nf++) {
                    asm volatile(
                        "mma.sync.aligned.m16n8k16.row.col.f32.bf16.bf16.f32 "
                        "{%0,%1,%2,%3}, {%4,%5,%6,%7}, {%8,%9}, {%0,%1,%2,%3};"
                        : "+f"(acc[mf][nf][0]), "+f"(acc[mf][nf][1]),
                          "+f"(acc[mf][nf][2]), "+f"(acc[mf][nf][3])
                        : "r"(a[mf][0]), "r"(a[mf][1]), "r"(a[mf][2]), "r"(a[mf][3]),
                          "r"(b[nf][0]), "r"(b[nf][1]));
                }
        }
    }

    // ---- epilogue: bias + relu; P = out*dinv (layers 0,1) or raw out (layer 2) ----
#pragma unroll
    for (int mf = 0; mf < 2; mf++) {
        int r1 = row0 + m0 + mf * 16 + gid;
        int r2 = r1 + 8;
        float sc1 = 1.f, sc2 = 1.f;
        if (layer < 2) {
            sc1 = (r1 < N) ? g_dinv[r1] : 0.f;
            sc2 = (r2 < N) ? g_dinv[r2] : 0.f;
        }
#pragma unroll
        for (int nf = 0; nf < 8; nf++) {
            int c = n0 + nf * 8 + tig * 2;
            float2 bb = *(const float2*)(bias + c);
            if (r1 < N) {
                float v0 = fmaxf(acc[mf][nf][0] + bb.x, 0.f);
                float v1 = fmaxf(acc[mf][nf][1] + bb.y, 0.f);
                *(float2*)(g_P + (size_t)r1 * 128 + c) = make_float2(v0 * sc1, v1 * sc1);
            }
            if (r2 < N) {
                float v2 = fmaxf(acc[mf][nf][2] + bb.x, 0.f);
                float v3 = fmaxf(acc[mf][nf][3] + bb.y, 0.f);
                *(float2*)(g_P + (size_t)r2 * 128 + c) = make_float2(v2 * sc2, v3 * sc2);
            }
        }
    }
}

// ===================== pooling + output linear (+ zero g_deg for next call) =====================
__global__ void __launch_bounds__(128) k_pool_out(const void* __restrict__ batch,
                                                  const float* __restrict__ out_w,
                                                  const float* __restrict__ out_b,
                                                  float* __restrict__ out, int N) {
    for (int i = blockIdx.x * blockDim.x + threadIdx.x; i < N; i += gridDim.x * blockDim.x)
        g_deg[i] = 0;

    int g = blockIdx.x;
    int d = threadIdx.x;
    int is64 = g_is64;
    const long long* b64 = (const long long*)batch;
    const int*       b32 = (const int*)batch;

    int lo, hi;
    { int a = 0, b = N; while (a < b) { int m = (a + b) >> 1;
        int bm = is64 ? (int)b64[m] : b32[m];
        if (bm < g) a = m + 1; else b = m; } lo = a; }
    { int a = lo, b = N; while (a < b) { int m = (a + b) >> 1;
        int bm = is64 ? (int)b64[m] : b32[m];
        if (bm < g + 1) a = m + 1; else b = m; } hi = a; }

    float s = 0.f, mx = 0.f;   // relu output >= 0: max init 0 matches segment_max for non-empty segments
    for (int n = lo; n < hi; n++) {
        float v = g_P[(size_t)n * 128 + d];   // g_P holds raw H3 after layer 2
        s += v;
        mx = fmaxf(mx, v);
    }
    float cnt  = fmaxf((float)(hi - lo), 1.f);
    float mean = s / cnt;

    __shared__ float sp[128][10];
#pragma unroll
    for (int j = 0; j < 10; j++)
        sp[d][j] = mx * out_w[d * 10 + j]
                 + mean * out_w[(128 + d) * 10 + j]
                 + s * out_w[(256 + d) * 10 + j];
    __syncthreads();

    if (d < 10) {
        float r = 0.f;
        for (int i = 0; i < 128; i++) r += sp[i][d];
        out[g * 10 + d] = r + out_b[d];
    }
}

// ===================== launch =====================
extern "C" void kernel_launch(void* const* d_in, const int* in_sizes, int n_in,
                              void* d_out, int out_size) {
    const float* x      = (const float*)d_in[0];
    const void*  edge   = d_in[1];
    const void*  batch  = d_in[2];
    const float* conv_w = (const float*)d_in[3];
    const float* conv_b = (const float*)d_in[4];
    const float* out_w  = (const float*)d_in[5];
    const float* out_b  = (const float*)d_in[6];
    float*       out    = (float*)d_out;

    int N = in_sizes[0] / 128;
    int E = in_sizes[1] / 2;

    const int SMEM_BYTES = 4 * TILE_H * 2;   // 139264, 1 CTA/SM (R13 best config)
    static bool attr_done = false;
    if (!attr_done) {
        cudaFuncSetAttribute(k_gemm_mma, cudaFuncAttributeMaxDynamicSharedMemorySize, SMEM_BYTES);
        attr_done = true;
    }

    int tiles = (N + 127) / 128;
    int gblk  = (N * 32 + 255) / 256;

    k_probe<<<1, 128>>>(edge);                                    // 1
    k_wconv<<<24, 256>>>(conv_w);                                 // 2
    k_scanfill<<<SF_GRID, 1024>>>(edge, E, N);                    // 3 (hist+scan+fill)
    k_gather<true><<<gblk, 256>>>(x, N);                          // 4  <- profiled
    k_gemm_mma<<<tiles, 256, SMEM_BYTES>>>(0, conv_b, N);         // 5
    k_gather<false><<<gblk, 256>>>(nullptr, N);                   // 6
    k_gemm_mma<<<tiles, 256, SMEM_BYTES>>>(1, conv_b + 128, N);   // 7
    k_gather<false><<<gblk, 256>>>(nullptr, N);                   // 8
    k_gemm_mma<<<tiles, 256, SMEM_BYTES>>>(2, conv_b + 256, N);   // 9
    k_pool_out<<<256, 128>>>(batch, out_w, out_b, out, N);        // 10
}

// round 16
// speedup vs baseline: 1.0522x; 1.0425x over previous
#include <cuda_runtime.h>
#include <cuda_bf16.h>
#include <cstdint>

#define NMAX 100000
#define EMAX 1600000
#define SF_GRID 96          // scanfill blocks (all co-resident on 148 SMs)
#define WC_BLKS 24          // extra blocks in the fused kernel doing W conversion

// Scratch (device globals — allocation-free per harness rules)
__device__ float  g_S[NMAX * 128];     // aggregated features S = A_hat * H
__device__ float  g_P[NMAX * 128];     // P = dinv .* H (layers 0,1); raw H3 (layer 2, for pool)
__device__ float  g_dinv[NMAX];
__device__ int    g_deg[NMAX];         // zeroed by previous call's pool (BSS zero on call 1)
__device__ int    g_cur[NMAX];
__device__ int    g_rptr[NMAX + 1];
__device__ int    g_col[EMAX];
__device__ int    g_blocksum[128];     // 0 = not ready (zero-init / pool-reset); agg | 1<<30 when published
__device__ int    g_done0, g_done1;    // pool-reset
__device__ int    g_is64;

// Pre-converted bf16 W images, B-layout [n][k] with rows padded to 136 halves.
#define BROW 136
__device__ __align__(16) unsigned short g_Wb[3][2][128 * BROW];

__device__ __forceinline__ uint32_t packbf(float x0, float x1) {
    return ((uint32_t)__bfloat16_as_ushort(__float2bfloat16(x1)) << 16)
         |  (uint32_t)__bfloat16_as_ushort(__float2bfloat16(x0));
}

// ===================== L1 (fused): wconv blocks + hist/scan/dinv/fill blocks =====================
__global__ void __launch_bounds__(1024) k_scanfill(const void* edge,
                                                   const float* __restrict__ conv_w,
                                                   int E, int N) {
    // block-local dtype probe (8 loads, L2-hit for all blocks)
    const long long* p64 = (const long long*)edge;
    int is64 = 1;
#pragma unroll
    for (int q = 0; q < 8; q++) {
        long long v = p64[q];
        if (v < 0 || v >= (1LL << 31)) is64 = 0;
    }

    int b = blockIdx.x, t = threadIdx.x;

    // ---- W-conversion blocks (exit before any spin barrier; co-residency of the 96 preserved) ----
    if (b >= SF_GRID) {
        int g = (b - SF_GRID) * 2 + (t >> 7);     // 2 units per block, threads 0..255
        if (t < 256 && g < 48) {
            int l = g >> 4;
            int c = (g & 15) * 8;
            int n = t & 127;
            const float* W = conv_w + (size_t)l * 16384;
            uint32_t hi[4], lo[4];
#pragma unroll
            for (int j = 0; j < 4; j++) {
                float v0 = W[(size_t)(c + 2 * j) * 128 + n];
                float v1 = W[(size_t)(c + 2 * j + 1) * 128 + n];
                float h0 = __bfloat162float(__float2bfloat16(v0));
                float h1 = __bfloat162float(__float2bfloat16(v1));
                hi[j] = packbf(v0, v1);
                lo[j] = packbf(v0 - h0, v1 - h1);
            }
            *(uint4*)&g_Wb[l][0][n * BROW + c] = make_uint4(hi[0], hi[1], hi[2], hi[3]);
            *(uint4*)&g_Wb[l][1][n * BROW + c] = make_uint4(lo[0], lo[1], lo[2], lo[3]);
        }
        return;
    }

    if (b == 0 && t == 0) g_is64 = is64;   // for k_pool_out

    __shared__ int ssum[1024];
    __shared__ int sbs[SF_GRID];
    __shared__ int sh_pref, sh_tot;

    const long long* e64 = (const long long*)edge;
    const int*       e32 = (const int*)edge;

    // ---- phase 0: degree histogram ----
    for (int e = b * 1024 + t; e < E; e += SF_GRID * 1024) {
        int d = is64 ? (int)e64[E + e] : e32[E + e];
        if ((unsigned)d < (unsigned)N) atomicAdd(&g_deg[d], 1);
    }
    __threadfence();
    __syncthreads();
    if (t == 0) {
        atomicAdd(&g_done0, 1);
        while (atomicAdd(&g_done0, 0) < SF_GRID) __nanosleep(128);
    }
    __syncthreads();

    // ---- phase 1: scan (decoupled lookback) + dinv ----
    int C = (N + SF_GRID - 1) / SF_GRID;
    int base = b * C;
    int lim  = min(base + C, N);
    int i0 = base + 2 * t;                     // consecutive pair (order-correct scan)
    int i1 = i0 + 1;
    int d0 = (i0 < lim) ? g_deg[i0] : 0;
    int d1 = (i1 < lim) ? g_deg[i1] : 0;
    int part = d0 + d1;

    ssum[t] = part;
    __syncthreads();
    for (int off = 1; off < 1024; off <<= 1) {
        int v = (t >= off) ? ssum[t - off] : 0;
        __syncthreads();
        ssum[t] += v;
        __syncthreads();
    }
    int incl = ssum[t];
    int agg  = ssum[1023];

    if (t == 0) atomicExch(&g_blocksum[b], agg | (1 << 30));   // publish (0 = not ready)

    if (t < SF_GRID) {
        int v;
        do { v = atomicAdd(&g_blocksum[t], 0); if (v != 0) break; __nanosleep(64); } while (1);
        sbs[t] = v & ~(1 << 30);
    }
    __syncthreads();
    if (t == 0) {
        int p = 0, tot = 0;
        for (int j = 0; j < SF_GRID; j++) { if (j < b) p += sbs[j]; tot += sbs[j]; }
        sh_pref = p; sh_tot = tot;
    }
    __syncthreads();

    int excl = sh_pref + incl - part;
    if (i0 < lim) {
        g_rptr[i0] = excl;
        atomicExch(&g_cur[i0], excl);
        g_dinv[i0] = rsqrtf((float)(d0 + 1));  // +1 self-loop
    }
    if (i1 < lim) {
        int e1 = excl + d0;
        g_rptr[i1] = e1;
        atomicExch(&g_cur[i1], e1);
        g_dinv[i1] = rsqrtf((float)(d1 + 1));
    }
    if (b == SF_GRID - 1 && t == 0) g_rptr[N] = sh_tot;

    __threadfence();
    __syncthreads();
    if (t == 0) {
        atomicAdd(&g_done1, 1);
        while (atomicAdd(&g_done1, 0) < SF_GRID) __nanosleep(128);
    }
    __syncthreads();

    // ---- phase 2: fill (bucket src by dst) ----
    for (int e = b * 1024 + t; e < E; e += SF_GRID * 1024) {
        int s, d;
        if (is64) { s = (int)e64[e]; d = (int)e64[E + e]; }
        else      { s = e32[e];      d = e32[E + e]; }
        if ((unsigned)d < (unsigned)N) {
            int pos = atomicAdd(&g_cur[d], 1);
            g_col[pos] = ((unsigned)s < (unsigned)N) ? s : 0;
        }
    }
}

// ===================== gather (R12 frozen form): S[d] = dinv[d]*(P[d] + sum P[src]) =====================
template<bool L0>
__global__ void __launch_bounds__(256) k_gather(const float* __restrict__ xin, int N) {
    int w = (blockIdx.x * 256 + threadIdx.x) >> 5;
    if (w >= N) return;
    int lane = threadIdx.x & 31;

    int s0 = g_rptr[w], s1 = g_rptr[w + 1];
    float dv = g_dinv[w];
    const float4* B4 = L0 ? (const float4*)xin : (const float4*)g_P;

    float4 acc = B4[(size_t)w * 32 + lane];       // self term
    if (L0) { acc.x *= dv; acc.y *= dv; acc.z *= dv; acc.w *= dv; }

    int e = s0;
    for (; e + 3 < s1; e += 4) {
        int sa = g_col[e], sb = g_col[e + 1], sc = g_col[e + 2], sd = g_col[e + 3];
        float4 va = B4[(size_t)sa * 32 + lane];
        float4 vb = B4[(size_t)sb * 32 + lane];
        float4 vc = B4[(size_t)sc * 32 + lane];
        float4 vd = B4[(size_t)sd * 32 + lane];
        if (L0) {
            float fa = g_dinv[sa], fb = g_dinv[sb], fc = g_dinv[sc], fd = g_dinv[sd];
            va.x *= fa; va.y *= fa; va.z *= fa; va.w *= fa;
            vb.x *= fb; vb.y *= fb; vb.z *= fb; vb.w *= fb;
            vc.x *= fc; vc.y *= fc; vc.z *= fc; vc.w *= fc;
            vd.x *= fd; vd.y *= fd; vd.z *= fd; vd.w *= fd;
        }
        acc.x += va.x + vb.x + vc.x + vd.x;
        acc.y += va.y + vb.y + vc.y + vd.y;
        acc.z += va.z + vb.z + vc.z + vd.z;
        acc.w += va.w + vb.w + vc.w + vd.w;
    }
    for (; e < s1; e++) {
        int s = g_col[e];
        float4 v = B4[(size_t)s * 32 + lane];
        if (L0) { float f = g_dinv[s]; v.x *= f; v.y *= f; v.z *= f; v.w *= f; }
        acc.x += v.x; acc.y += v.y; acc.z += v.z; acc.w += v.w;
    }

    acc.x *= dv; acc.y *= dv; acc.z *= dv; acc.w *= dv;
    ((float4*)g_S)[(size_t)w * 32 + lane] = acc;
}

// ===================== mma.sync GEMM (R13 frozen form): out = relu(S @ W + b) =====================
#define TILE_H (128 * BROW)

__global__ void __launch_bounds__(256, 1) k_gemm_mma(int layer, const float* __restrict__ bias,
                                                     int N) {
    extern __shared__ unsigned short sm[];
    int tid  = threadIdx.x;
    int lane = tid & 31;
    int wid  = tid >> 5;
    int row0 = blockIdx.x * 128;

    unsigned short* Ah = sm;
    unsigned short* Al = sm + TILE_H;
    unsigned short* Bh = sm + 2 * TILE_H;
    unsigned short* Bl = sm + 3 * TILE_H;

    // ---- stage A = g_S: fp32 -> bf16 hi(truncated)/lo ----
#pragma unroll
    for (int i = 0; i < 8; i++) {
        int j = tid + i * 256;
        int r = j >> 4;
        int c = (j & 15) << 3;
        float v[8];
        if (row0 + r < N) {
            float4 a = *(const float4*)(g_S + (size_t)(row0 + r) * 128 + c);
            float4 b = *(const float4*)(g_S + (size_t)(row0 + r) * 128 + c + 4);
            v[0] = a.x; v[1] = a.y; v[2] = a.z; v[3] = a.w;
            v[4] = b.x; v[5] = b.y; v[6] = b.z; v[7] = b.w;
        } else {
#pragma unroll
            for (int q = 0; q < 8; q++) v[q] = 0.f;
        }
        uint32_t hi[4], lo[4];
#pragma unroll
        for (int q = 0; q < 4; q++) {
            float x0 = v[2 * q], x1 = v[2 * q + 1];
            uint32_t u0 = __float_as_uint(x0), u1 = __float_as_uint(x1);
            hi[q] = __byte_perm(u0, u1, 0x7632);   // {hi16(x0), hi16(x1)}
            float l0 = x0 - __uint_as_float(u0 & 0xFFFF0000u);
            float l1 = x1 - __uint_as_float(u1 & 0xFFFF0000u);
            asm("cvt.rn.bf16x2.f32 %0, %1, %2;" : "=r"(lo[q]) : "f"(l1), "f"(l0));
        }
        *(uint4*)&Ah[r * BROW + c] = make_uint4(hi[0], hi[1], hi[2], hi[3]);
        *(uint4*)&Al[r * BROW + c] = make_uint4(lo[0], lo[1], lo[2], lo[3]);
    }

    // ---- copy W images ----
    {
        const uint4* wh = (const uint4*)g_Wb[layer][0];
        const uint4* wl = (const uint4*)g_Wb[layer][1];
        uint4* bh = (uint4*)Bh;
        uint4* bl = (uint4*)Bl;
        for (int j = tid; j < (TILE_H / 8); j += 256) {
            bh[j] = wh[j];
            bl[j] = wl[j];
        }
    }
    __syncthreads();

    int wm = wid & 3;
    int wn = wid >> 2;
    int m0 = wm * 32;
    int n0 = wn * 64;
    int gid = lane >> 2;
    int tig = lane & 3;

    float acc[2][8][4];
#pragma unroll
    for (int mf = 0; mf < 2; mf++)
#pragma unroll
        for (int nf = 0; nf < 8; nf++)
#pragma unroll
            for (int q = 0; q < 4; q++) acc[mf][nf][q] = 0.f;

    for (int s = 0; s < 3; s++) {
        const unsigned short* Asel = (s == 2) ? Al : Ah;
        const unsigned short* Bsel = (s == 1) ? Bl : Bh;
#pragma unroll
        for (int k = 0; k < 8; k++) {
            int k0 = k * 16;
            uint32_t a[2][4];
#pragma unroll
            for (int mf = 0; mf < 2; mf++) {
                int rr = m0 + mf * 16;
                a[mf][0] = *(const uint32_t*)&Asel[(rr + gid)     * BROW + k0 + tig * 2];
                a[mf][1] = *(const uint32_t*)&Asel[(rr + gid + 8) * BROW + k0 + tig * 2];
                a[mf][2] = *(const uint32_t*)&Asel[(rr + gid)     * BROW + k0 + 8 + tig * 2];
                a[mf][3] = *(const uint32_t*)&Asel[(rr + gid + 8) * BROW + k0 + 8 + tig * 2];
            }
            uint32_t b[8][2];
#pragma unroll
            for (int nf = 0; nf < 8; nf++) {
                int n = n0 + nf * 8 + gid;
                b[nf][0] = *(const uint32_t*)&Bsel[n * BROW + k0 + tig * 2];
                b[nf][1] = *(const uint32_t*)&Bsel[n * BROW + k0 + 8 + tig * 2];
            }
#pragma unroll
            for (int mf = 0; mf < 2; mf++)
#pragma unroll
                for (int nf = 0; nf < 8; nf++) {
                    asm volatile(
                        "mma.sync.aligned.m16n8k16.row.col.f32.bf16.bf16.f32 "
                        "{%0,%1,%2,%3}, {%4,%5,%6,%7}, {%8,%9}, {%0,%1,%2,%3};"
                        : "+f"(acc[mf][nf][0]), "+f"(acc[mf][nf][1]),
                          "+f"(acc[mf][nf][2]), "+f"(acc[mf][nf][3])
                        : "r"(a[mf][0]), "r"(a[mf][1]), "r"(a[mf][2]), "r"(a[mf][3]),
                          "r"(b[nf][0]), "r"(b[nf][1]));
                }
        }
    }

    // ---- epilogue: bias + relu; P = out*dinv (layers 0,1) or raw out (layer 2) ----
#pragma unroll
    for (int mf = 0; mf < 2; mf++) {
        int r1 = row0 + m0 + mf * 16 + gid;
        int r2 = r1 + 8;
        float sc1 = 1.f, sc2 = 1.f;
        if (layer < 2) {
            sc1 = (r1 < N) ? g_dinv[r1] : 0.f;
            sc2 = (r2 < N) ? g_dinv[r2] : 0.f;
        }
#pragma unroll
        for (int nf = 0; nf < 8; nf++) {
            int c = n0 + nf * 8 + tig * 2;
            float2 bb = *(const float2*)(bias + c);
            if (r1 < N) {
                float v0 = fmaxf(acc[mf][nf][0] + bb.x, 0.f);
                float v1 = fmaxf(acc[mf][nf][1] + bb.y, 0.f);
                *(float2*)(g_P + (size_t)r1 * 128 + c) = make_float2(v0 * sc1, v1 * sc1);
            }
            if (r2 < N) {
                float v2 = fmaxf(acc[mf][nf][2] + bb.x, 0.f);
                float v3 = fmaxf(acc[mf][nf][3] + bb.y, 0.f);
                *(float2*)(g_P + (size_t)r2 * 128 + c) = make_float2(v2 * sc2, v3 * sc2);
            }
        }
    }
}

// ===================== pooling + output linear (+ resets for next replay) =====================
// Thread layout: 32 col-groups x 4 row-phases; float4 loads, 4 rows in flight.
__global__ void __launch_bounds__(128) k_pool_out(const void* __restrict__ batch,
                                                  const float* __restrict__ out_w,
                                                  const float* __restrict__ out_b,
                                                  float* __restrict__ out, int N) {
    // resets for the next replay (BSS zero covers call 1)
    for (int i = blockIdx.x * blockDim.x + threadIdx.x; i < N; i += gridDim.x * blockDim.x)
        g_deg[i] = 0;
    if (blockIdx.x == 0) {
        if (threadIdx.x < 128) g_blocksum[threadIdx.x] = 0;
        if (threadIdx.x == 0) { g_done0 = 0; g_done1 = 0; }
    }

    int g = blockIdx.x;
    int t = threadIdx.x;
    int is64 = g_is64;
    const long long* b64 = (const long long*)batch;
    const int*       b32 = (const int*)batch;

    int lo, hi;
    { int a = 0, b = N; while (a < b) { int m = (a + b) >> 1;
        int bm = is64 ? (int)b64[m] : b32[m];
        if (bm < g) a = m + 1; else b = m; } lo = a; }
    { int a = lo, b = N; while (a < b) { int m = (a + b) >> 1;
        int bm = is64 ? (int)b64[m] : b32[m];
        if (bm < g + 1) a = m + 1; else b = m; } hi = a; }

    int c4 = (t & 31) * 4;    // 4 columns per thread
    int rp = t >> 5;          // row phase 0..3

    float4 s4 = make_float4(0.f, 0.f, 0.f, 0.f);
    float4 m4 = make_float4(0.f, 0.f, 0.f, 0.f);   // relu output >= 0
    for (int n = lo + rp; n < hi; n += 4) {
        float4 v = *(const float4*)(g_P + (size_t)n * 128 + c4);
        s4.x += v.x; s4.y += v.y; s4.z += v.z; s4.w += v.w;
        m4.x = fmaxf(m4.x, v.x); m4.y = fmaxf(m4.y, v.y);
        m4.z = fmaxf(m4.z, v.z); m4.w = fmaxf(m4.w, v.w);
    }

    // combine the 4 row-phases
    __shared__ float ss[4][128];
    __shared__ float sx[4][128];
    *(float4*)&ss[rp][c4] = s4;
    *(float4*)&sx[rp][c4] = m4;
    __syncthreads();

    int d = t;   // 0..127
    float s  = ss[0][d] + ss[1][d] + ss[2][d] + ss[3][d];
    float mx = fmaxf(fmaxf(sx[0][d], sx[1][d]), fmaxf(sx[2][d], sx[3][d]));
    float cnt  = fmaxf((float)(hi - lo), 1.f);
    float mean = s / cnt;

    __shared__ float sp[128][10];
#pragma unroll
    for (int j = 0; j < 10; j++)
        sp[d][j] = mx * out_w[d * 10 + j]
                 + mean * out_w[(128 + d) * 10 + j]
                 + s * out_w[(256 + d) * 10 + j];
    __syncthreads();

    if (d < 10) {
        float r = 0.f;
        for (int i = 0; i < 128; i++) r += sp[i][d];
        out[g * 10 + d] = r + out_b[d];
    }
}

// ===================== launch =====================
extern "C" void kernel_launch(void* const* d_in, const int* in_sizes, int n_in,
                              void* d_out, int out_size) {
    const float* x      = (const float*)d_in[0];
    const void*  edge   = d_in[1];
    const void*  batch  = d_in[2];
    const float* conv_w = (const float*)d_in[3];
    const float* conv_b = (const float*)d_in[4];
    const float* out_w  = (const float*)d_in[5];
    const float* out_b  = (const float*)d_in[6];
    float*       out    = (float*)d_out;

    int N = in_sizes[0] / 128;
    int E = in_sizes[1] / 2;

    const int SMEM_BYTES = 4 * TILE_H * 2;   // 139264, 1 CTA/SM (R13 frozen config)
    static bool attr_done = false;
    if (!attr_done) {
        cudaFuncSetAttribute(k_gemm_mma, cudaFuncAttributeMaxDynamicSharedMemorySize, SMEM_BYTES);
        attr_done = true;
    }

    int tiles = (N + 127) / 128;
    int gblk  = (N * 32 + 255) / 256;

    k_scanfill<<<SF_GRID + WC_BLKS, 1024>>>(edge, conv_w, E, N);  // 1 (probe+wconv+hist+scan+fill)
    k_gather<true><<<gblk, 256>>>(x, N);                          // 2
    k_gemm_mma<<<tiles, 256, SMEM_BYTES>>>(0, conv_b, N);         // 3
    k_gather<false><<<gblk, 256>>>(nullptr, N);                   // 4  <- profiled
    k_gemm_mma<<<tiles, 256, SMEM_BYTES>>>(1, conv_b + 128, N);   // 5
    k_gather<false><<<gblk, 256>>>(nullptr, N);                   // 6
    k_gemm_mma<<<tiles, 256, SMEM_BYTES>>>(2, conv_b + 256, N);   // 7
    k_pool_out<<<256, 128>>>(batch, out_w, out_b, out, N);        // 8
}